// round 6
// baseline (speedup 1.0000x reference)
#include <cuda_runtime.h>

// ---------------- scratch (sizes fixed: N=50000, E=400000) ----------------
__device__ float g_agg [50048  * 80];   // per-node gated sums: 32 silu'd scalars + 48 vec comps
__device__ float g_agg2[50048  * 40];   // after Lms/Lmv fold: 16 s + 24 v
__device__ float g_midT[40 * 400000];   // stage-1 intermediate, channel-major [40][E]
__device__ float g_esT [ 8 * 400000];   // edge_s transposed [8][E]
__device__ float g_evT [24 * 400000];   // edge_v transposed [24][E]
__device__ float g_gate[16 * 400000];   // sigmoid gates, t-major [16][E]
__device__ float g_hid [48 * 50048];    // update hidden scalars (silu'd / sigm'd), t-major
__device__ float g_hidv[48 * 50048];    // update gated vector comps, (k*3+c)-major

#define I2f   0.70710678118654752f
#define I3f   0.57735026918962576f
#define R128f 0.08838834764831845f
#define R32f  0.17677669529663687f

__device__ __forceinline__ float sigm_f(float x) {
    return __fdividef(1.f, 1.f + __expf(-x));
}

__device__ __forceinline__ void wload(float* __restrict__ dst, const float* __restrict__ src,
                                      int nf4, float sc, int tid, int nt) {
    for (int t = tid; t < nf4; t += nt) {
        float4 v = reinterpret_cast<const float4*>(src)[t];
        v.x *= sc; v.y *= sc; v.z *= sc; v.w *= sc;
        reinterpret_cast<float4*>(dst)[t] = v;
    }
}
__device__ __forceinline__ void wslice(float* __restrict__ dst, const float* __restrict__ src,
                                       int rows, int srcF4, int dstF4, int off4,
                                       float sc, int tid) {
    int n = rows * dstF4;
    for (int t = tid; t < n; t += 128) {
        int r = t / dstF4, o = t - r * dstF4;
        float4 v = reinterpret_cast<const float4*>(src)[r * srcF4 + off4 + o];
        v.x *= sc; v.y *= sc; v.z *= sc; v.w *= sc;
        reinterpret_cast<float4*>(dst)[t] = v;
    }
}

template<int K4>
__device__ __forceinline__ void fma_k(float* acc, const float* __restrict__ w, float p) {
#pragma unroll
    for (int k = 0; k < K4; k++) {
        float4 ww = reinterpret_cast<const float4*>(w)[k];
        acc[4 * k + 0] += p * ww.x; acc[4 * k + 1] += p * ww.y;
        acc[4 * k + 2] += p * ww.z; acc[4 * k + 3] += p * ww.w;
    }
}
__device__ __forceinline__ void fma_vo8(float* vo, const float* A, float bx, float by, float bz) {
#pragma unroll
    for (int k = 0; k < 8; k++) {
        vo[3 * k + 0] += A[k] * bx; vo[3 * k + 1] += A[k] * by; vo[3 * k + 2] += A[k] * bz;
    }
}
__device__ __forceinline__ void fma_cross8(float* vo, const float* __restrict__ w,
                                           float cx, float cy, float cz) {
#pragma unroll
    for (int q = 0; q < 2; q++) {
        float4 ww = reinterpret_cast<const float4*>(w)[q];
        vo[12 * q + 0]  += cx * ww.x; vo[12 * q + 1]  += cy * ww.x; vo[12 * q + 2]  += cz * ww.x;
        vo[12 * q + 3]  += cx * ww.y; vo[12 * q + 4]  += cy * ww.y; vo[12 * q + 5]  += cz * ww.y;
        vo[12 * q + 6]  += cx * ww.z; vo[12 * q + 7]  += cy * ww.z; vo[12 * q + 8]  += cz * ww.z;
        vo[12 * q + 9]  += cx * ww.w; vo[12 * q + 10] += cy * ww.w; vo[12 * q + 11] += cz * ww.w;
    }
}
__device__ __forceinline__ void ld_f(float* dst, const float* __restrict__ src, int nf4) {
#pragma unroll
    for (int q = 0; q < 6; q++)
        if (q < nf4) reinterpret_cast<float4*>(dst)[q] =
            __ldg(reinterpret_cast<const float4*>(src) + q);
}
// coalesced channel-major load: dst[t] = base[t*E + e]
template<int NCH>
__device__ __forceinline__ void ld_t(float* dst, const float* __restrict__ base, int e, int E) {
#pragma unroll
    for (int t = 0; t < NCH; t++) dst[t] = __ldg(base + (size_t)t * E + e);
}

// ---------------- kernels ----------------
__global__ void zero_kernel(int n) {
    int i = blockIdx.x * 256 + threadIdx.x;
    if (i < n) g_agg[i] = 0.f;
}

// transpose edge attrs to channel-major (one-off; reads strided, writes coalesced)
__global__ void transpose_edges_kernel(const float* __restrict__ es,
                                       const float* __restrict__ ev, int E) {
    int e = blockIdx.x * 256 + threadIdx.x;
    if (e >= E) return;
    float b[24];
#pragma unroll
    for (int q = 0; q < 2; q++)
        reinterpret_cast<float4*>(b)[q] = __ldg(reinterpret_cast<const float4*>(es + (size_t)e * 8) + q);
#pragma unroll
    for (int t = 0; t < 8; t++) g_esT[(size_t)t * E + e] = b[t];
#pragma unroll
    for (int q = 0; q < 6; q++)
        reinterpret_cast<float4*>(b)[q] = __ldg(reinterpret_cast<const float4*>(ev + (size_t)e * 24) + q);
#pragma unroll
    for (int t = 0; t < 24; t++) g_evT[(size_t)t * E + e] = b[t];
}

// stage1 scalar paths: ms[16] -> g_midT[0:16)[e]
__global__ __launch_bounds__(128, 6) void stage1_s_kernel(
    const float* __restrict__ ns, const float* __restrict__ nv,
    const int* __restrict__ eidx,
    const float* __restrict__ W1ss, const float* __restrict__ W1vvs, int E)
{
    __shared__ float wss[4096], wd[1024];
    int tid = threadIdx.x;
    wload(wss, W1ss, 1024, I2f / 16.f, tid, 128);
    wload(wd, W1vvs, 256, I2f * I3f / 8.f, tid, 128);
    __syncthreads();
    int e = blockIdx.x * 128 + tid;
    if (e >= E) return;
    int r = eidx[e], c = eidx[E + e];

    float acc[16];
#pragma unroll
    for (int k = 0; k < 16; k++) acc[k] = 0.f;
    {
        float s1[16], s2[16];
        ld_f(s1, ns + (size_t)r * 16, 4);
        ld_f(s2, ns + (size_t)c * 16, 4);
#pragma unroll 1
        for (int i = 0; i < 16; i++) {
            float a = s1[i];
#pragma unroll 2
            for (int j = 0; j < 16; j++)
                fma_k<4>(acc, &wss[(i * 16 + j) * 16], a * s2[j]);
        }
    }
    {
        float v1[24], v2[24];
        ld_f(v1, nv + (size_t)r * 24, 6);
        ld_f(v2, nv + (size_t)c * 24, 6);
#pragma unroll 1
        for (int i = 0; i < 8; i++) {
            float ax = v1[3 * i], ay = v1[3 * i + 1], az = v1[3 * i + 2];
#pragma unroll 2
            for (int j = 0; j < 8; j++) {
                float d = ax * v2[3 * j] + ay * v2[3 * j + 1] + az * v2[3 * j + 2];
                fma_k<4>(acc, &wd[(i * 8 + j) * 16], d);
            }
        }
    }
#pragma unroll
    for (int k = 0; k < 16; k++) g_midT[(size_t)k * E + e] = acc[k];
}

// stage1 vector paths: mv[8][3] -> g_midT[16:40)[e]
__global__ __launch_bounds__(128, 6) void stage1_v_kernel(
    const float* __restrict__ ns, const float* __restrict__ nv,
    const int* __restrict__ eidx,
    const float* __restrict__ W1sv, const float* __restrict__ W1vs,
    const float* __restrict__ W1vvv, int E)
{
    __shared__ float wsv[1024], wvs[1024], wvvv[512];
    int tid = threadIdx.x;
    wload(wsv, W1sv, 256, I3f * R128f, tid, 128);
    wload(wvs, W1vs, 256, I3f * R128f, tid, 128);
    wload(wvvv, W1vvv, 128, I2f * I3f / 8.f, tid, 128);
    __syncthreads();
    int e = blockIdx.x * 128 + tid;
    if (e >= E) return;
    int r = eidx[e], c = eidx[E + e];

    float vo[24];
#pragma unroll
    for (int k = 0; k < 24; k++) vo[k] = 0.f;
    float v2[24];
    ld_f(v2, nv + (size_t)c * 24, 6);
    {   // 0x1 -> 1
        float s1[16];
        ld_f(s1, ns + (size_t)r * 16, 4);
#pragma unroll 1
        for (int j = 0; j < 8; j++) {
            float A[8];
#pragma unroll
            for (int k = 0; k < 8; k++) A[k] = 0.f;
#pragma unroll 2
            for (int i = 0; i < 16; i++)
                fma_k<2>(A, &wsv[(i * 8 + j) * 8], s1[i]);
            fma_vo8(vo, A, v2[3 * j], v2[3 * j + 1], v2[3 * j + 2]);
        }
    }
    float v1[24];
    ld_f(v1, nv + (size_t)r * 24, 6);
    {   // 1x0 -> 1
        float s2[16];
        ld_f(s2, ns + (size_t)c * 16, 4);
#pragma unroll 1
        for (int i = 0; i < 8; i++) {
            float A[8];
#pragma unroll
            for (int k = 0; k < 8; k++) A[k] = 0.f;
#pragma unroll 2
            for (int j = 0; j < 16; j++)
                fma_k<2>(A, &wvs[(i * 16 + j) * 8], s2[j]);
            fma_vo8(vo, A, v1[3 * i], v1[3 * i + 1], v1[3 * i + 2]);
        }
    }
    // 1x1 -> 1
#pragma unroll 1
    for (int i = 0; i < 8; i++) {
        float ax = v1[3 * i], ay = v1[3 * i + 1], az = v1[3 * i + 2];
#pragma unroll 1
        for (int j = 0; j < 8; j++) {
            float bx = v2[3 * j], by = v2[3 * j + 1], bz = v2[3 * j + 2];
            fma_cross8(vo, &wvvv[(i * 8 + j) * 8],
                       ay * bz - az * by, az * bx - ax * bz, ax * by - ay * bx);
        }
    }
#pragma unroll
    for (int t = 0; t < 24; t++) g_midT[(size_t)(16 + t) * E + e] = vo[t];
}

// stage2 scalar paths, 3 k-chunks of 16. chunks 0,1: silu -> atomic agg. chunk 2: sigm -> g_gate.
__global__ __launch_bounds__(128, 5) void stage2_s_kernel(
    const int* __restrict__ eidx,
    const float* __restrict__ W2ss, const float* __restrict__ W2vvs, int E)
{
    __shared__ float ws[2048], wd[1024];
    int tid = threadIdx.x;
    int e = blockIdx.x * 128 + tid;
    bool act = e < E;
    int c = 0;
    float ms[16], mv[24], es[8], ev[24];
    if (act) {
        c = eidx[E + e];
        ld_t<16>(ms, g_midT, e, E);
        ld_t<24>(mv, g_midT + (size_t)16 * E, e, E);
        ld_t<8>(es, g_esT, e, E);
        ld_t<24>(ev, g_evT, e, E);
    }
#pragma unroll 1
    for (int ch = 0; ch < 3; ch++) {
        __syncthreads();
        wslice(ws, W2ss, 128, 12, 4, ch * 4, I2f * R128f, tid);
        wslice(wd, W2vvs, 64, 12, 4, ch * 4, I2f * I3f / 8.f, tid);
        __syncthreads();
        if (!act) continue;
        float acc[16];
#pragma unroll
        for (int k = 0; k < 16; k++) acc[k] = 0.f;
#pragma unroll 1
        for (int i = 0; i < 16; i++) {
            float a = ms[i];
#pragma unroll 2
            for (int j = 0; j < 8; j++)
                fma_k<4>(acc, &ws[(i * 8 + j) * 16], a * es[j]);
        }
#pragma unroll 1
        for (int i = 0; i < 8; i++) {
            float ax = mv[3 * i], ay = mv[3 * i + 1], az = mv[3 * i + 2];
#pragma unroll 2
            for (int j = 0; j < 8; j++) {
                float d = ax * ev[3 * j] + ay * ev[3 * j + 1] + az * ev[3 * j + 2];
                fma_k<4>(acc, &wd[(i * 8 + j) * 16], d);
            }
        }
        if (ch < 2) {
            float* dst = &g_agg[(size_t)c * 80 + ch * 16];
#pragma unroll
            for (int t = 0; t < 16; t++)
                atomicAdd(dst + t, acc[t] * sigm_f(acc[t]));   // silu
        } else {
#pragma unroll
            for (int t = 0; t < 16; t++)
                g_gate[(size_t)t * E + e] = sigm_f(acc[t]);
        }
    }
}

// stage2 vector paths, 2 k-chunks of 8. gate from g_gate, atomic into agg vec slots.
__global__ __launch_bounds__(128, 5) void stage2_v_kernel(
    const int* __restrict__ eidx,
    const float* __restrict__ W2sv, const float* __restrict__ W2vs,
    const float* __restrict__ W2vvv, int E)
{
    __shared__ float wsv[1024], wvs[1024], wvvv[512];
    int tid = threadIdx.x;
    int e = blockIdx.x * 128 + tid;
    bool act = e < E;
    int c = 0;
    float ms[16], mv[24], es[8], ev[24];
    if (act) {
        c = eidx[E + e];
        ld_t<16>(ms, g_midT, e, E);
        ld_t<24>(mv, g_midT + (size_t)16 * E, e, E);
        ld_t<8>(es, g_esT, e, E);
        ld_t<24>(ev, g_evT, e, E);
    }
#pragma unroll 1
    for (int ch = 0; ch < 2; ch++) {
        __syncthreads();
        wslice(wsv, W2sv, 128, 4, 2, ch * 2, I3f * R128f, tid);
        wslice(wvs, W2vs, 64, 4, 2, ch * 2, I3f / 8.f, tid);
        wslice(wvvv, W2vvv, 64, 4, 2, ch * 2, I2f * I3f / 8.f, tid);
        __syncthreads();
        if (!act) continue;
        float vo[24];
#pragma unroll
        for (int k = 0; k < 24; k++) vo[k] = 0.f;
#pragma unroll 1
        for (int j = 0; j < 8; j++) {
            float A[8];
#pragma unroll
            for (int k = 0; k < 8; k++) A[k] = 0.f;
#pragma unroll 2
            for (int i = 0; i < 16; i++)
                fma_k<2>(A, &wsv[(i * 8 + j) * 8], ms[i]);
            fma_vo8(vo, A, ev[3 * j], ev[3 * j + 1], ev[3 * j + 2]);
        }
#pragma unroll 1
        for (int i = 0; i < 8; i++) {
            float A[8];
#pragma unroll
            for (int k = 0; k < 8; k++) A[k] = 0.f;
#pragma unroll 2
            for (int j = 0; j < 8; j++)
                fma_k<2>(A, &wvs[(i * 8 + j) * 8], es[j]);
            fma_vo8(vo, A, mv[3 * i], mv[3 * i + 1], mv[3 * i + 2]);
        }
#pragma unroll 1
        for (int i = 0; i < 8; i++) {
            float ax = mv[3 * i], ay = mv[3 * i + 1], az = mv[3 * i + 2];
#pragma unroll 1
            for (int j = 0; j < 8; j++) {
                float bx = ev[3 * j], by = ev[3 * j + 1], bz = ev[3 * j + 2];
                fma_cross8(vo, &wvvv[(i * 8 + j) * 8],
                           ay * bz - az * by, az * bx - ax * bz, ax * by - ay * bx);
            }
        }
#pragma unroll
        for (int t = 0; t < 8; t++) {
            float g = g_gate[(size_t)(ch * 8 + t) * E + e];
            float* dst = &g_agg[(size_t)c * 80 + 32 + (ch * 8 + t) * 3];
            atomicAdd(dst + 0, vo[3 * t + 0] * g);
            atomicAdd(dst + 1, vo[3 * t + 1] * g);
            atomicAdd(dst + 2, vo[3 * t + 2] * g);
        }
    }
}

// fold Lms/Lmv into aggregated (post-gate) sums: g_agg[N,80] -> g_agg2[N,40]
__global__ void fold_kernel(const float* __restrict__ Lms, const float* __restrict__ Lmv, int N)
{
    __shared__ float lms[512], lmv[128];
    int tid = threadIdx.x;
    wload(lms, Lms, 128, R32f, tid, 256);
    wload(lmv, Lmv, 32, 0.25f, tid, 256);
    __syncthreads();
    int n = blockIdx.x * 256 + tid;
    if (n >= N) return;
    const float* a = &g_agg[(size_t)n * 80];
    float* o = &g_agg2[(size_t)n * 40];
    float os[16];
#pragma unroll
    for (int k = 0; k < 16; k++) os[k] = 0.f;
#pragma unroll 1
    for (int i = 0; i < 32; i++)
        fma_k<4>(os, &lms[i * 16], a[i]);
#pragma unroll
    for (int k = 0; k < 16; k++) o[k] = os[k];
    float ov[24];
#pragma unroll
    for (int k = 0; k < 24; k++) ov[k] = 0.f;
#pragma unroll 1
    for (int i = 0; i < 16; i++) {
        float ax = a[32 + 3 * i], ay = a[32 + 3 * i + 1], az = a[32 + 3 * i + 2];
        const float* w = &lmv[i * 8];
#pragma unroll
        for (int k = 0; k < 8; k++) {
            float ww = w[k];
            ov[3 * k + 0] += ax * ww; ov[3 * k + 1] += ay * ww; ov[3 * k + 2] += az * ww;
        }
    }
#pragma unroll
    for (int t = 0; t < 24; t++) o[16 + t] = ov[t];
}

// update scalar paths -> g_hid (silu'd for k<32, sigm'd for k>=32)
__global__ __launch_bounds__(128, 5) void update_s_kernel(
    const float* __restrict__ ns, const float* __restrict__ nv,
    const float* __restrict__ W3ss, const float* __restrict__ W3vvs, int N)
{
    __shared__ float ws[4096], wd[1024];
    int tid = threadIdx.x;
    int n = blockIdx.x * 128 + tid;
    bool act = n < N;
    float s1[16], v1[24], s2[16], v2[24];
    if (act) {
        ld_f(s1, ns + (size_t)n * 16, 4);
        ld_f(v1, nv + (size_t)n * 24, 6);
        const float* a = &g_agg2[(size_t)n * 40];
#pragma unroll
        for (int q = 0; q < 4; q++) reinterpret_cast<float4*>(s2)[q] = reinterpret_cast<const float4*>(a)[q];
#pragma unroll
        for (int q = 0; q < 6; q++) reinterpret_cast<float4*>(v2)[q] = reinterpret_cast<const float4*>(a)[4 + q];
    }
#pragma unroll 1
    for (int ch = 0; ch < 3; ch++) {
        __syncthreads();
        wslice(ws, W3ss, 256, 12, 4, ch * 4, I2f / 16.f, tid);
        wslice(wd, W3vvs, 64, 12, 4, ch * 4, I2f * I3f / 8.f, tid);
        __syncthreads();
        if (!act) continue;
        float acc[16];
#pragma unroll
        for (int k = 0; k < 16; k++) acc[k] = 0.f;
#pragma unroll 1
        for (int i = 0; i < 16; i++) {
            float a = s1[i];
#pragma unroll 2
            for (int j = 0; j < 16; j++)
                fma_k<4>(acc, &ws[(i * 16 + j) * 16], a * s2[j]);
        }
#pragma unroll 1
        for (int i = 0; i < 8; i++) {
            float ax = v1[3 * i], ay = v1[3 * i + 1], az = v1[3 * i + 2];
#pragma unroll 2
            for (int j = 0; j < 8; j++) {
                float d = ax * v2[3 * j] + ay * v2[3 * j + 1] + az * v2[3 * j + 2];
                fma_k<4>(acc, &wd[(i * 8 + j) * 16], d);
            }
        }
#pragma unroll
        for (int t = 0; t < 16; t++) {
            float v = (ch < 2) ? acc[t] * sigm_f(acc[t]) : sigm_f(acc[t]);
            g_hid[(size_t)(ch * 16 + t) * N + n] = v;
        }
    }
}

// update vector paths -> gated comps in g_hidv
__global__ __launch_bounds__(128, 5) void update_v_kernel(
    const float* __restrict__ ns, const float* __restrict__ nv,
    const float* __restrict__ W3sv, const float* __restrict__ W3vs,
    const float* __restrict__ W3vvv, int N)
{
    __shared__ float wsv[1024], wvs[1024], wvvv[512];
    int tid = threadIdx.x;
    int n = blockIdx.x * 128 + tid;
    bool act = n < N;
    float s1[16], v1[24], s2[16], v2[24];
    if (act) {
        ld_f(s1, ns + (size_t)n * 16, 4);
        ld_f(v1, nv + (size_t)n * 24, 6);
        const float* a = &g_agg2[(size_t)n * 40];
#pragma unroll
        for (int q = 0; q < 4; q++) reinterpret_cast<float4*>(s2)[q] = reinterpret_cast<const float4*>(a)[q];
#pragma unroll
        for (int q = 0; q < 6; q++) reinterpret_cast<float4*>(v2)[q] = reinterpret_cast<const float4*>(a)[4 + q];
    }
#pragma unroll 1
    for (int ch = 0; ch < 2; ch++) {
        __syncthreads();
        wslice(wsv, W3sv, 128, 4, 2, ch * 2, I3f * R128f, tid);
        wslice(wvs, W3vs, 128, 4, 2, ch * 2, I3f * R128f, tid);
        wslice(wvvv, W3vvv, 64, 4, 2, ch * 2, I2f * I3f / 8.f, tid);
        __syncthreads();
        if (!act) continue;
        float vo[24];
#pragma unroll
        for (int k = 0; k < 24; k++) vo[k] = 0.f;
#pragma unroll 1
    for (int j = 0; j < 8; j++) {
            float A[8];
#pragma unroll
            for (int k = 0; k < 8; k++) A[k] = 0.f;
#pragma unroll 2
            for (int i = 0; i < 16; i++)
                fma_k<2>(A, &wsv[(i * 8 + j) * 8], s1[i]);
            fma_vo8(vo, A, v2[3 * j], v2[3 * j + 1], v2[3 * j + 2]);
        }
#pragma unroll 1
        for (int i = 0; i < 8; i++) {
            float A[8];
#pragma unroll
            for (int k = 0; k < 8; k++) A[k] = 0.f;
#pragma unroll 2
            for (int j = 0; j < 16; j++)
                fma_k<2>(A, &wvs[(i * 16 + j) * 8], s2[j]);
            fma_vo8(vo, A, v1[3 * i], v1[3 * i + 1], v1[3 * i + 2]);
        }
#pragma unroll 1
        for (int i = 0; i < 8; i++) {
            float ax = v1[3 * i], ay = v1[3 * i + 1], az = v1[3 * i + 2];
#pragma unroll 1
            for (int j = 0; j < 8; j++) {
                float bx = v2[3 * j], by = v2[3 * j + 1], bz = v2[3 * j + 2];
                float cx = ay * bz - az * by, cy = az * bx - ax * bz, cz = ax * by - ay * bx;
                fma_cross8(vo, &wvvv[(i * 8 + j) * 8], cx, cy, cz);
            }
        }
#pragma unroll
        for (int t = 0; t < 8; t++) {
            float g = g_hid[(size_t)(32 + ch * 8 + t) * N + n];
#pragma unroll
            for (int cc = 0; cc < 3; cc++)
                g_hidv[(size_t)((ch * 8 + t) * 3 + cc) * N + n] = vo[3 * t + cc] * g;
        }
    }
}

// final: apply Lus/Luv per node, write out[N,40]
__global__ void final_kernel(const float* __restrict__ Lus, const float* __restrict__ Luv,
                             float* __restrict__ out, int N)
{
    __shared__ float lus[512], luv[128];
    int tid = threadIdx.x;
    wload(lus, Lus, 128, R32f, tid, 256);
    wload(luv, Luv, 32, 0.25f, tid, 256);
    __syncthreads();
    int n = blockIdx.x * 256 + tid;
    if (n >= N) return;
    float os[16];
#pragma unroll
    for (int k = 0; k < 16; k++) os[k] = 0.f;
#pragma unroll 1
    for (int i = 0; i < 32; i++)
        fma_k<4>(os, &lus[i * 16], g_hid[(size_t)i * N + n]);
    float ov[24];
#pragma unroll
    for (int k = 0; k < 24; k++) ov[k] = 0.f;
#pragma unroll 1
    for (int i = 0; i < 16; i++) {
        float ax = g_hidv[(size_t)(3 * i + 0) * N + n];
        float ay = g_hidv[(size_t)(3 * i + 1) * N + n];
        float az = g_hidv[(size_t)(3 * i + 2) * N + n];
        const float* w = &luv[i * 8];
#pragma unroll
        for (int k = 0; k < 8; k++) {
            float ww = w[k];
            ov[3 * k + 0] += ax * ww; ov[3 * k + 1] += ay * ww; ov[3 * k + 2] += az * ww;
        }
    }
    float* o = out + (size_t)n * 40;
#pragma unroll
    for (int k = 0; k < 16; k++) o[k] = os[k];
#pragma unroll
    for (int t = 0; t < 24; t++) o[16 + t] = ov[t];
}

// ---------------- launch ----------------
extern "C" void kernel_launch(void* const* d_in, const int* in_sizes, int n_in,
                              void* d_out, int out_size) {
    const float* node_s = (const float*)d_in[0];
    const float* node_v = (const float*)d_in[1];
    const float* edge_s = (const float*)d_in[3];
    const float* edge_v = (const float*)d_in[4];
    const int*   eidx   = (const int*)d_in[5];
    const float* W1ss = (const float*)d_in[6];
    const float* W1sv = (const float*)d_in[7];
    const float* W1vs = (const float*)d_in[8];
    const float* W1vvs = (const float*)d_in[9];
    const float* W1vvv = (const float*)d_in[10];
    const float* W2ss = (const float*)d_in[11];
    const float* W2sv = (const float*)d_in[12];
    const float* W2vs = (const float*)d_in[13];
    const float* W2vvs = (const float*)d_in[14];
    const float* W2vvv = (const float*)d_in[15];
    const float* Lms = (const float*)d_in[16];
    const float* Lmv = (const float*)d_in[17];
    const float* W3ss = (const float*)d_in[18];
    const float* W3sv = (const float*)d_in[19];
    const float* W3vs = (const float*)d_in[20];
    const float* W3vvs = (const float*)d_in[21];
    const float* W3vvv = (const float*)d_in[22];
    const float* Lus = (const float*)d_in[23];
    const float* Luv = (const float*)d_in[24];
    float* out = (float*)d_out;

    int N = in_sizes[0] / 16;
    int E = in_sizes[3] / 8;
    int gE = (E + 127) / 128;
    int gN = (N + 127) / 128;

    zero_kernel<<<(N * 80 + 255) / 256, 256>>>(N * 80);
    transpose_edges_kernel<<<(E + 255) / 256, 256>>>(edge_s, edge_v, E);
    stage1_s_kernel<<<gE, 128>>>(node_s, node_v, eidx, W1ss, W1vvs, E);
    stage1_v_kernel<<<gE, 128>>>(node_s, node_v, eidx, W1sv, W1vs, W1vvv, E);
    stage2_s_kernel<<<gE, 128>>>(eidx, W2ss, W2vvs, E);
    stage2_v_kernel<<<gE, 128>>>(eidx, W2sv, W2vs, W2vvv, E);
    fold_kernel<<<(N + 255) / 256, 256>>>(Lms, Lmv, N);
    update_s_kernel<<<gN, 128>>>(node_s, node_v, W3ss, W3vvs, N);
    update_v_kernel<<<gN, 128>>>(node_s, node_v, W3sv, W3vs, W3vvv, N);
    final_kernel<<<(N + 255) / 256, 256>>>(Lus, Luv, out, N);
}

// round 7
// speedup vs baseline: 1.5596x; 1.5596x over previous
#include <cuda_runtime.h>

// ---------------- scratch (sizes fixed: N=50000, E=400000) ----------------
__device__ float g_agg [50048  * 80];   // per-node gated sums: 32 silu'd scalars + 48 vec comps
__device__ float g_agg2[50048  * 40];   // after Lms/Lmv fold: 16 s + 24 v
__device__ float g_mid [400000 * 40];   // stage-1 per-edge intermediate (e-major)
__device__ float g_gate[16 * 400000];   // sigmoid gates, t-major [16][E]
__device__ float g_hid [48 * 50048];    // update hidden scalars (silu'd / sigm'd), t-major
__device__ float g_hidv[48 * 50048];    // update gated vector comps, (k*3+c)-major

#define I2f   0.70710678118654752f
#define I3f   0.57735026918962576f
#define R128f 0.08838834764831845f
#define R32f  0.17677669529663687f

using u64 = unsigned long long;

__device__ __forceinline__ float sigm_f(float x) {
    return __fdividef(1.f, 1.f + __expf(-x));
}

// ---- packed fp32x2 helpers (Blackwell FFMA2; exact fp32) ----
__device__ __forceinline__ void ffma2(u64& a, u64 w, u64 p) {
    asm("fma.rn.f32x2 %0, %1, %2, %0;" : "+l"(a) : "l"(w), "l"(p));
}
__device__ __forceinline__ u64 pack2(float x, float y) {
    u64 r; asm("mov.b64 %0, {%1, %2};" : "=l"(r) : "f"(x), "f"(y)); return r;
}
__device__ __forceinline__ float2 unpk(u64 v) {
    float2 t; asm("mov.b64 {%0, %1}, %2;" : "=f"(t.x), "=f"(t.y) : "l"(v)); return t;
}
// acc: P pairs (2P consecutive k); w: 2P floats, 16B-aligned
template<int P>
__device__ __forceinline__ void fma_kp(u64* acc, const float* __restrict__ w, u64 pp) {
#pragma unroll
    for (int m = 0; m < P; m += 2) {
        ulonglong2 ww = reinterpret_cast<const ulonglong2*>(w)[m >> 1];
        ffma2(acc[m], ww.x, pp);
        ffma2(acc[m + 1], ww.y, pp);
    }
}
// 8-wide k of 3-component vec accumulators vs one weight row (8 floats)
__device__ __forceinline__ void fma_vec8(u64* vx, u64* vy, u64* vz, const float* __restrict__ w,
                                         u64 cx2, u64 cy2, u64 cz2) {
#pragma unroll
    for (int m = 0; m < 4; m += 2) {
        ulonglong2 ww = reinterpret_cast<const ulonglong2*>(w)[m >> 1];
        ffma2(vx[m], ww.x, cx2); ffma2(vx[m + 1], ww.y, cx2);
        ffma2(vy[m], ww.x, cy2); ffma2(vy[m + 1], ww.y, cy2);
        ffma2(vz[m], ww.x, cz2); ffma2(vz[m + 1], ww.y, cz2);
    }
}
// A (4 pairs) times packed scalar comps into vec accumulators
__device__ __forceinline__ void fma_avec(u64* vx, u64* vy, u64* vz, const u64* A,
                                         u64 bx2, u64 by2, u64 bz2) {
#pragma unroll
    for (int m = 0; m < 4; m++) {
        ffma2(vx[m], A[m], bx2);
        ffma2(vy[m], A[m], by2);
        ffma2(vz[m], A[m], bz2);
    }
}
__device__ __forceinline__ void unpack_vec(const u64* vx, const u64* vy, const u64* vz, float* vo) {
#pragma unroll
    for (int m = 0; m < 4; m++) {
        float2 x = unpk(vx[m]), y = unpk(vy[m]), z = unpk(vz[m]);
        vo[3 * (2 * m) + 0] = x.x; vo[3 * (2 * m) + 1] = y.x; vo[3 * (2 * m) + 2] = z.x;
        vo[3 * (2 * m + 1) + 0] = x.y; vo[3 * (2 * m + 1) + 1] = y.y; vo[3 * (2 * m + 1) + 2] = z.y;
    }
}

__device__ __forceinline__ void wload(float* __restrict__ dst, const float* __restrict__ src,
                                      int nf4, float sc, int tid, int nt) {
    for (int t = tid; t < nf4; t += nt) {
        float4 v = reinterpret_cast<const float4*>(src)[t];
        v.x *= sc; v.y *= sc; v.z *= sc; v.w *= sc;
        reinterpret_cast<float4*>(dst)[t] = v;
    }
}
__device__ __forceinline__ void wslice(float* __restrict__ dst, const float* __restrict__ src,
                                       int rows, int srcF4, int dstF4, int off4,
                                       float sc, int tid) {
    int n = rows * dstF4;
    for (int t = tid; t < n; t += 128) {
        int r = t / dstF4, o = t - r * dstF4;
        float4 v = reinterpret_cast<const float4*>(src)[r * srcF4 + off4 + o];
        v.x *= sc; v.y *= sc; v.z *= sc; v.w *= sc;
        reinterpret_cast<float4*>(dst)[t] = v;
    }
}
template<int K4>
__device__ __forceinline__ void fma_k(float* acc, const float* __restrict__ w, float p) {
#pragma unroll
    for (int k = 0; k < K4; k++) {
        float4 ww = reinterpret_cast<const float4*>(w)[k];
        acc[4 * k + 0] += p * ww.x; acc[4 * k + 1] += p * ww.y;
        acc[4 * k + 2] += p * ww.z; acc[4 * k + 3] += p * ww.w;
    }
}
__device__ __forceinline__ void ld_f(float* dst, const float* __restrict__ src, int nf4) {
#pragma unroll
    for (int q = 0; q < 6; q++)
        if (q < nf4) reinterpret_cast<float4*>(dst)[q] =
            __ldg(reinterpret_cast<const float4*>(src) + q);
}

// ---------------- kernels ----------------
__global__ void zero_kernel(int n) {
    int i = blockIdx.x * 256 + threadIdx.x;
    if (i < n) g_agg[i] = 0.f;
}

// stage1 scalar paths: ms[16] -> g_mid[e][0:16)
__global__ __launch_bounds__(128, 6) void stage1_s_kernel(
    const float* __restrict__ ns, const float* __restrict__ nv,
    const int* __restrict__ eidx,
    const float* __restrict__ W1ss, const float* __restrict__ W1vvs, int E)
{
    __shared__ float wss[4096], wd[1024];
    int tid = threadIdx.x;
    wload(wss, W1ss, 1024, I2f / 16.f, tid, 128);
    wload(wd, W1vvs, 256, I2f * I3f / 8.f, tid, 128);
    __syncthreads();
    int e = blockIdx.x * 128 + tid;
    if (e >= E) return;
    int r = eidx[e], c = eidx[E + e];

    u64 acc[8];
#pragma unroll
    for (int m = 0; m < 8; m++) acc[m] = 0ull;
    {
        float s1[16], s2[16];
        ld_f(s1, ns + (size_t)r * 16, 4);
        ld_f(s2, ns + (size_t)c * 16, 4);
#pragma unroll 1
        for (int i = 0; i < 16; i++) {
            float a = s1[i];
#pragma unroll 2
            for (int j = 0; j < 16; j++) {
                float p = a * s2[j];
                fma_kp<8>(acc, &wss[(i * 16 + j) * 16], pack2(p, p));
            }
        }
    }
    {
        float v1[24], v2[24];
        ld_f(v1, nv + (size_t)r * 24, 6);
        ld_f(v2, nv + (size_t)c * 24, 6);
#pragma unroll 1
        for (int i = 0; i < 8; i++) {
            float ax = v1[3 * i], ay = v1[3 * i + 1], az = v1[3 * i + 2];
#pragma unroll 2
            for (int j = 0; j < 8; j++) {
                float d = ax * v2[3 * j] + ay * v2[3 * j + 1] + az * v2[3 * j + 2];
                fma_kp<8>(acc, &wd[(i * 8 + j) * 16], pack2(d, d));
            }
        }
    }
    float accf[16];
#pragma unroll
    for (int m = 0; m < 8; m++) { float2 t = unpk(acc[m]); accf[2 * m] = t.x; accf[2 * m + 1] = t.y; }
    float* o = &g_mid[(size_t)e * 40];
#pragma unroll
    for (int q = 0; q < 4; q++)
        reinterpret_cast<float4*>(o)[q] = reinterpret_cast<float4*>(accf)[q];
}

// stage1 vector paths: mv[8][3] -> g_mid[e][16:40)
__global__ __launch_bounds__(128, 6) void stage1_v_kernel(
    const float* __restrict__ ns, const float* __restrict__ nv,
    const int* __restrict__ eidx,
    const float* __restrict__ W1sv, const float* __restrict__ W1vs,
    const float* __restrict__ W1vvv, int E)
{
    __shared__ float wsv[1024], wvs[1024], wvvv[512];
    int tid = threadIdx.x;
    wload(wsv, W1sv, 256, I3f * R128f, tid, 128);
    wload(wvs, W1vs, 256, I3f * R128f, tid, 128);
    wload(wvvv, W1vvv, 128, I2f * I3f / 8.f, tid, 128);
    __syncthreads();
    int e = blockIdx.x * 128 + tid;
    if (e >= E) return;
    int r = eidx[e], c = eidx[E + e];

    u64 vx[4], vy[4], vz[4];
#pragma unroll
    for (int m = 0; m < 4; m++) { vx[m] = 0ull; vy[m] = 0ull; vz[m] = 0ull; }
    float v2[24];
    ld_f(v2, nv + (size_t)c * 24, 6);
    {   // 0x1 -> 1
        float s1[16];
        ld_f(s1, ns + (size_t)r * 16, 4);
#pragma unroll 1
        for (int j = 0; j < 8; j++) {
            u64 A[4];
#pragma unroll
            for (int m = 0; m < 4; m++) A[m] = 0ull;
#pragma unroll 2
            for (int i = 0; i < 16; i++)
                fma_kp<4>(A, &wsv[(i * 8 + j) * 8], pack2(s1[i], s1[i]));
            fma_avec(vx, vy, vz, A,
                     pack2(v2[3 * j], v2[3 * j]), pack2(v2[3 * j + 1], v2[3 * j + 1]),
                     pack2(v2[3 * j + 2], v2[3 * j + 2]));
        }
    }
    float v1[24];
    ld_f(v1, nv + (size_t)r * 24, 6);
    {   // 1x0 -> 1
        float s2[16];
        ld_f(s2, ns + (size_t)c * 16, 4);
#pragma unroll 1
        for (int i = 0; i < 8; i++) {
            u64 A[4];
#pragma unroll
            for (int m = 0; m < 4; m++) A[m] = 0ull;
#pragma unroll 2
            for (int j = 0; j < 16; j++)
                fma_kp<4>(A, &wvs[(i * 16 + j) * 8], pack2(s2[j], s2[j]));
            fma_avec(vx, vy, vz, A,
                     pack2(v1[3 * i], v1[3 * i]), pack2(v1[3 * i + 1], v1[3 * i + 1]),
                     pack2(v1[3 * i + 2], v1[3 * i + 2]));
        }
    }
    // 1x1 -> 1 (cross)
#pragma unroll 1
    for (int i = 0; i < 8; i++) {
        float ax = v1[3 * i], ay = v1[3 * i + 1], az = v1[3 * i + 2];
#pragma unroll 1
        for (int j = 0; j < 8; j++) {
            float bx = v2[3 * j], by = v2[3 * j + 1], bz = v2[3 * j + 2];
            float cx = ay * bz - az * by, cy = az * bx - ax * bz, cz = ax * by - ay * bx;
            fma_vec8(vx, vy, vz, &wvvv[(i * 8 + j) * 8],
                     pack2(cx, cx), pack2(cy, cy), pack2(cz, cz));
        }
    }
    float vo[24];
    unpack_vec(vx, vy, vz, vo);
    float* o = &g_mid[(size_t)e * 40 + 16];
#pragma unroll
    for (int q = 0; q < 6; q++)
        reinterpret_cast<float4*>(o)[q] = reinterpret_cast<float4*>(vo)[q];
}

// stage2 scalar paths, 3 k-chunks of 16. chunks 0,1: silu -> atomic agg. chunk 2: sigm -> g_gate.
__global__ __launch_bounds__(128, 5) void stage2_s_kernel(
    const float* __restrict__ edge_s, const float* __restrict__ edge_v,
    const int* __restrict__ eidx,
    const float* __restrict__ W2ss, const float* __restrict__ W2vvs, int E)
{
    __shared__ float ws[2048], wd[1024];
    int tid = threadIdx.x;
    int e = blockIdx.x * 128 + tid;
    bool act = e < E;
    int c = 0;
    float ms[16], mv[24], es[8], ev[24];
    if (act) {
        c = eidx[E + e];
        const float* m = &g_mid[(size_t)e * 40];
#pragma unroll
        for (int q = 0; q < 4; q++) reinterpret_cast<float4*>(ms)[q] = reinterpret_cast<const float4*>(m)[q];
#pragma unroll
        for (int q = 0; q < 6; q++) reinterpret_cast<float4*>(mv)[q] = reinterpret_cast<const float4*>(m)[4 + q];
        ld_f(es, edge_s + (size_t)e * 8, 2);
        ld_f(ev, edge_v + (size_t)e * 24, 6);
    }
#pragma unroll 1
    for (int ch = 0; ch < 3; ch++) {
        __syncthreads();
        wslice(ws, W2ss, 128, 12, 4, ch * 4, I2f * R128f, tid);
        wslice(wd, W2vvs, 64, 12, 4, ch * 4, I2f * I3f / 8.f, tid);
        __syncthreads();
        if (!act) continue;
        u64 acc[8];
#pragma unroll
        for (int m = 0; m < 8; m++) acc[m] = 0ull;
#pragma unroll 1
        for (int i = 0; i < 16; i++) {
            float a = ms[i];
#pragma unroll 2
            for (int j = 0; j < 8; j++) {
                float p = a * es[j];
                fma_kp<8>(acc, &ws[(i * 8 + j) * 16], pack2(p, p));
            }
        }
#pragma unroll 1
        for (int i = 0; i < 8; i++) {
            float ax = mv[3 * i], ay = mv[3 * i + 1], az = mv[3 * i + 2];
#pragma unroll 2
            for (int j = 0; j < 8; j++) {
                float d = ax * ev[3 * j] + ay * ev[3 * j + 1] + az * ev[3 * j + 2];
                fma_kp<8>(acc, &wd[(i * 8 + j) * 16], pack2(d, d));
            }
        }
        float accf[16];
#pragma unroll
        for (int m = 0; m < 8; m++) { float2 t = unpk(acc[m]); accf[2 * m] = t.x; accf[2 * m + 1] = t.y; }
        if (ch < 2) {
            float* dst = &g_agg[(size_t)c * 80 + ch * 16];
#pragma unroll
            for (int t = 0; t < 16; t++)
                atomicAdd(dst + t, accf[t] * sigm_f(accf[t]));   // silu
        } else {
#pragma unroll
            for (int t = 0; t < 16; t++)
                g_gate[(size_t)t * E + e] = sigm_f(accf[t]);
        }
    }
}

// stage2 vector paths, 2 k-chunks of 8. gate from g_gate, atomic into agg vec slots.
__global__ __launch_bounds__(128, 5) void stage2_v_kernel(
    const float* __restrict__ edge_s, const float* __restrict__ edge_v,
    const int* __restrict__ eidx,
    const float* __restrict__ W2sv, const float* __restrict__ W2vs,
    const float* __restrict__ W2vvv, int E)
{
    __shared__ float wsv[1024], wvs[1024], wvvv[512];
    int tid = threadIdx.x;
    int e = blockIdx.x * 128 + tid;
    bool act = e < E;
    int c = 0;
    float ms[16], mv[24], es[8], ev[24];
    if (act) {
        c = eidx[E + e];
        const float* m = &g_mid[(size_t)e * 40];
#pragma unroll
        for (int q = 0; q < 4; q++) reinterpret_cast<float4*>(ms)[q] = reinterpret_cast<const float4*>(m)[q];
#pragma unroll
        for (int q = 0; q < 6; q++) reinterpret_cast<float4*>(mv)[q] = reinterpret_cast<const float4*>(m)[4 + q];
        ld_f(es, edge_s + (size_t)e * 8, 2);
        ld_f(ev, edge_v + (size_t)e * 24, 6);
    }
#pragma unroll 1
    for (int ch = 0; ch < 2; ch++) {
        __syncthreads();
        wslice(wsv, W2sv, 128, 4, 2, ch * 2, I3f * R128f, tid);
        wslice(wvs, W2vs, 64, 4, 2, ch * 2, I3f / 8.f, tid);
        wslice(wvvv, W2vvv, 64, 4, 2, ch * 2, I2f * I3f / 8.f, tid);
        __syncthreads();
        if (!act) continue;
        u64 vx[4], vy[4], vz[4];
#pragma unroll
        for (int m = 0; m < 4; m++) { vx[m] = 0ull; vy[m] = 0ull; vz[m] = 0ull; }
#pragma unroll 1
        for (int j = 0; j < 8; j++) {
            u64 A[4];
#pragma unroll
            for (int m = 0; m < 4; m++) A[m] = 0ull;
#pragma unroll 2
            for (int i = 0; i < 16; i++)
                fma_kp<4>(A, &wsv[(i * 8 + j) * 8], pack2(ms[i], ms[i]));
            fma_avec(vx, vy, vz, A,
                     pack2(ev[3 * j], ev[3 * j]), pack2(ev[3 * j + 1], ev[3 * j + 1]),
                     pack2(ev[3 * j + 2], ev[3 * j + 2]));
        }
#pragma unroll 1
        for (int i = 0; i < 8; i++) {
            u64 A[4];
#pragma unroll
            for (int m = 0; m < 4; m++) A[m] = 0ull;
#pragma unroll 2
            for (int j = 0; j < 8; j++)
                fma_kp<4>(A, &wvs[(i * 8 + j) * 8], pack2(es[j], es[j]));
            fma_avec(vx, vy, vz, A,
                     pack2(mv[3 * i], mv[3 * i]), pack2(mv[3 * i + 1], mv[3 * i + 1]),
                     pack2(mv[3 * i + 2], mv[3 * i + 2]));
        }
#pragma unroll 1
        for (int i = 0; i < 8; i++) {
            float ax = mv[3 * i], ay = mv[3 * i + 1], az = mv[3 * i + 2];
#pragma unroll 1
            for (int j = 0; j < 8; j++) {
                float bx = ev[3 * j], by = ev[3 * j + 1], bz = ev[3 * j + 2];
                float cx = ay * bz - az * by, cy = az * bx - ax * bz, cz = ax * by - ay * bx;
                fma_vec8(vx, vy, vz, &wvvv[(i * 8 + j) * 8],
                         pack2(cx, cx), pack2(cy, cy), pack2(cz, cz));
            }
        }
        float vo[24];
        unpack_vec(vx, vy, vz, vo);
#pragma unroll
        for (int t = 0; t < 8; t++) {
            float g = g_gate[(size_t)(ch * 8 + t) * E + e];
            float* dst = &g_agg[(size_t)c * 80 + 32 + (ch * 8 + t) * 3];
            atomicAdd(dst + 0, vo[3 * t + 0] * g);
            atomicAdd(dst + 1, vo[3 * t + 1] * g);
            atomicAdd(dst + 2, vo[3 * t + 2] * g);
        }
    }
}

// fold Lms/Lmv into aggregated (post-gate) sums: g_agg[N,80] -> g_agg2[N,40]
__global__ void fold_kernel(const float* __restrict__ Lms, const float* __restrict__ Lmv, int N)
{
    __shared__ float lms[512], lmv[128];
    int tid = threadIdx.x;
    wload(lms, Lms, 128, R32f, tid, 256);
    wload(lmv, Lmv, 32, 0.25f, tid, 256);
    __syncthreads();
    int n = blockIdx.x * 256 + tid;
    if (n >= N) return;
    const float* a = &g_agg[(size_t)n * 80];
    float* o = &g_agg2[(size_t)n * 40];
    float os[16];
#pragma unroll
    for (int k = 0; k < 16; k++) os[k] = 0.f;
#pragma unroll 1
    for (int i = 0; i < 32; i++)
        fma_k<4>(os, &lms[i * 16], a[i]);
#pragma unroll
    for (int k = 0; k < 16; k++) o[k] = os[k];
    float ov[24];
#pragma unroll
    for (int k = 0; k < 24; k++) ov[k] = 0.f;
#pragma unroll 1
    for (int i = 0; i < 16; i++) {
        float ax = a[32 + 3 * i], ay = a[32 + 3 * i + 1], az = a[32 + 3 * i + 2];
        const float* w = &lmv[i * 8];
#pragma unroll
        for (int k = 0; k < 8; k++) {
            float ww = w[k];
            ov[3 * k + 0] += ax * ww; ov[3 * k + 1] += ay * ww; ov[3 * k + 2] += az * ww;
        }
    }
#pragma unroll
    for (int t = 0; t < 24; t++) o[16 + t] = ov[t];
}

// update scalar paths -> g_hid (silu'd for k<32, sigm'd for k>=32)
__global__ __launch_bounds__(128, 5) void update_s_kernel(
    const float* __restrict__ ns, const float* __restrict__ nv,
    const float* __restrict__ W3ss, const float* __restrict__ W3vvs, int N)
{
    __shared__ float ws[4096], wd[1024];
    int tid = threadIdx.x;
    int n = blockIdx.x * 128 + tid;
    bool act = n < N;
    float s1[16], v1[24], s2[16], v2[24];
    if (act) {
        ld_f(s1, ns + (size_t)n * 16, 4);
        ld_f(v1, nv + (size_t)n * 24, 6);
        const float* a = &g_agg2[(size_t)n * 40];
#pragma unroll
        for (int q = 0; q < 4; q++) reinterpret_cast<float4*>(s2)[q] = reinterpret_cast<const float4*>(a)[q];
#pragma unroll
        for (int q = 0; q < 6; q++) reinterpret_cast<float4*>(v2)[q] = reinterpret_cast<const float4*>(a)[4 + q];
    }
#pragma unroll 1
    for (int ch = 0; ch < 3; ch++) {
        __syncthreads();
        wslice(ws, W3ss, 256, 12, 4, ch * 4, I2f / 16.f, tid);
        wslice(wd, W3vvs, 64, 12, 4, ch * 4, I2f * I3f / 8.f, tid);
        __syncthreads();
        if (!act) continue;
        u64 acc[8];
#pragma unroll
        for (int m = 0; m < 8; m++) acc[m] = 0ull;
#pragma unroll 1
        for (int i = 0; i < 16; i++) {
            float a = s1[i];
#pragma unroll 2
            for (int j = 0; j < 16; j++) {
                float p = a * s2[j];
                fma_kp<8>(acc, &ws[(i * 16 + j) * 16], pack2(p, p));
            }
        }
#pragma unroll 1
        for (int i = 0; i < 8; i++) {
            float ax = v1[3 * i], ay = v1[3 * i + 1], az = v1[3 * i + 2];
#pragma unroll 2
            for (int j = 0; j < 8; j++) {
                float d = ax * v2[3 * j] + ay * v2[3 * j + 1] + az * v2[3 * j + 2];
                fma_kp<8>(acc, &wd[(i * 8 + j) * 16], pack2(d, d));
            }
        }
        float accf[16];
#pragma unroll
        for (int m = 0; m < 8; m++) { float2 t = unpk(acc[m]); accf[2 * m] = t.x; accf[2 * m + 1] = t.y; }
#pragma unroll
        for (int t = 0; t < 16; t++) {
            float v = (ch < 2) ? accf[t] * sigm_f(accf[t]) : sigm_f(accf[t]);
            g_hid[(size_t)(ch * 16 + t) * N + n] = v;
        }
    }
}

// update vector paths -> gated comps in g_hidv
__global__ __launch_bounds__(128, 5) void update_v_kernel(
    const float* __restrict__ ns, const float* __restrict__ nv,
    const float* __restrict__ W3sv, const float* __restrict__ W3vs,
    const float* __restrict__ W3vvv, int N)
{
    __shared__ float wsv[1024], wvs[1024], wvvv[512];
    int tid = threadIdx.x;
    int n = blockIdx.x * 128 + tid;
    bool act = n < N;
    float s1[16], v1[24], s2[16], v2[24];
    if (act) {
        ld_f(s1, ns + (size_t)n * 16, 4);
        ld_f(v1, nv + (size_t)n * 24, 6);
        const float* a = &g_agg2[(size_t)n * 40];
#pragma unroll
        for (int q = 0; q < 4; q++) reinterpret_cast<float4*>(s2)[q] = reinterpret_cast<const float4*>(a)[q];
#pragma unroll
        for (int q = 0; q < 6; q++) reinterpret_cast<float4*>(v2)[q] = reinterpret_cast<const float4*>(a)[4 + q];
    }
#pragma unroll 1
    for (int ch = 0; ch < 2; ch++) {
        __syncthreads();
        wslice(wsv, W3sv, 128, 4, 2, ch * 2, I3f * R128f, tid);
        wslice(wvs, W3vs, 128, 4, 2, ch * 2, I3f * R128f, tid);
        wslice(wvvv, W3vvv, 64, 4, 2, ch * 2, I2f * I3f / 8.f, tid);
        __syncthreads();
        if (!act) continue;
        u64 vx[4], vy[4], vz[4];
#pragma unroll
        for (int m = 0; m < 4; m++) { vx[m] = 0ull; vy[m] = 0ull; vz[m] = 0ull; }
#pragma unroll 1
        for (int j = 0; j < 8; j++) {
            u64 A[4];
#pragma unroll
            for (int m = 0; m < 4; m++) A[m] = 0ull;
#pragma unroll 2
            for (int i = 0; i < 16; i++)
                fma_kp<4>(A, &wsv[(i * 8 + j) * 8], pack2(s1[i], s1[i]));
            fma_avec(vx, vy, vz, A,
                     pack2(v2[3 * j], v2[3 * j]), pack2(v2[3 * j + 1], v2[3 * j + 1]),
                     pack2(v2[3 * j + 2], v2[3 * j + 2]));
        }
#pragma unroll 1
        for (int i = 0; i < 8; i++) {
            u64 A[4];
#pragma unroll
            for (int m = 0; m < 4; m++) A[m] = 0ull;
#pragma unroll 2
            for (int j = 0; j < 16; j++)
                fma_kp<4>(A, &wvs[(i * 16 + j) * 8], pack2(s2[j], s2[j]));
            fma_avec(vx, vy, vz, A,
                     pack2(v1[3 * i], v1[3 * i]), pack2(v1[3 * i + 1], v1[3 * i + 1]),
                     pack2(v1[3 * i + 2], v1[3 * i + 2]));
        }
#pragma unroll 1
        for (int i = 0; i < 8; i++) {
            float ax = v1[3 * i], ay = v1[3 * i + 1], az = v1[3 * i + 2];
#pragma unroll 1
            for (int j = 0; j < 8; j++) {
                float bx = v2[3 * j], by = v2[3 * j + 1], bz = v2[3 * j + 2];
                float cx = ay * bz - az * by, cy = az * bx - ax * bz, cz = ax * by - ay * bx;
                fma_vec8(vx, vy, vz, &wvvv[(i * 8 + j) * 8],
                         pack2(cx, cx), pack2(cy, cy), pack2(cz, cz));
            }
        }
        float vo[24];
        unpack_vec(vx, vy, vz, vo);
#pragma unroll
        for (int t = 0; t < 8; t++) {
            float g = g_hid[(size_t)(32 + ch * 8 + t) * N + n];
#pragma unroll
            for (int cc = 0; cc < 3; cc++)
                g_hidv[(size_t)((ch * 8 + t) * 3 + cc) * N + n] = vo[3 * t + cc] * g;
        }
    }
}

// final: apply Lus/Luv per node, write out[N,40]
__global__ void final_kernel(const float* __restrict__ Lus, const float* __restrict__ Luv,
                             float* __restrict__ out, int N)
{
    __shared__ float lus[512], luv[128];
    int tid = threadIdx.x;
    wload(lus, Lus, 128, R32f, tid, 256);
    wload(luv, Luv, 32, 0.25f, tid, 256);
    __syncthreads();
    int n = blockIdx.x * 256 + tid;
    if (n >= N) return;
    float os[16];
#pragma unroll
    for (int k = 0; k < 16; k++) os[k] = 0.f;
#pragma unroll 1
    for (int i = 0; i < 32; i++)
        fma_k<4>(os, &lus[i * 16], g_hid[(size_t)i * N + n]);
    float ov[24];
#pragma unroll
    for (int k = 0; k < 24; k++) ov[k] = 0.f;
#pragma unroll 1
    for (int i = 0; i < 16; i++) {
        float ax = g_hidv[(size_t)(3 * i + 0) * N + n];
        float ay = g_hidv[(size_t)(3 * i + 1) * N + n];
        float az = g_hidv[(size_t)(3 * i + 2) * N + n];
        const float* w = &luv[i * 8];
#pragma unroll
        for (int k = 0; k < 8; k++) {
            float ww = w[k];
            ov[3 * k + 0] += ax * ww; ov[3 * k + 1] += ay * ww; ov[3 * k + 2] += az * ww;
        }
    }
    float* o = out + (size_t)n * 40;
#pragma unroll
    for (int k = 0; k < 16; k++) o[k] = os[k];
#pragma unroll
    for (int t = 0; t < 24; t++) o[16 + t] = ov[t];
}

// ---------------- launch ----------------
extern "C" void kernel_launch(void* const* d_in, const int* in_sizes, int n_in,
                              void* d_out, int out_size) {
    const float* node_s = (const float*)d_in[0];
    const float* node_v = (const float*)d_in[1];
    const float* edge_s = (const float*)d_in[3];
    const float* edge_v = (const float*)d_in[4];
    const int*   eidx   = (const int*)d_in[5];
    const float* W1ss = (const float*)d_in[6];
    const float* W1sv = (const float*)d_in[7];
    const float* W1vs = (const float*)d_in[8];
    const float* W1vvs = (const float*)d_in[9];
    const float* W1vvv = (const float*)d_in[10];
    const float* W2ss = (const float*)d_in[11];
    const float* W2sv = (const float*)d_in[12];
    const float* W2vs = (const float*)d_in[13];
    const float* W2vvs = (const float*)d_in[14];
    const float* W2vvv = (const float*)d_in[15];
    const float* Lms = (const float*)d_in[16];
    const float* Lmv = (const float*)d_in[17];
    const float* W3ss = (const float*)d_in[18];
    const float* W3sv = (const float*)d_in[19];
    const float* W3vs = (const float*)d_in[20];
    const float* W3vvs = (const float*)d_in[21];
    const float* W3vvv = (const float*)d_in[22];
    const float* Lus = (const float*)d_in[23];
    const float* Luv = (const float*)d_in[24];
    float* out = (float*)d_out;

    int N = in_sizes[0] / 16;
    int E = in_sizes[3] / 8;
    int gE = (E + 127) / 128;
    int gN = (N + 127) / 128;

    zero_kernel<<<(N * 80 + 255) / 256, 256>>>(N * 80);
    stage1_s_kernel<<<gE, 128>>>(node_s, node_v, eidx, W1ss, W1vvs, E);
    stage1_v_kernel<<<gE, 128>>>(node_s, node_v, eidx, W1sv, W1vs, W1vvv, E);
    stage2_s_kernel<<<gE, 128>>>(edge_s, edge_v, eidx, W2ss, W2vvs, E);
    stage2_v_kernel<<<gE, 128>>>(edge_s, edge_v, eidx, W2sv, W2vs, W2vvv, E);
    fold_kernel<<<(N + 255) / 256, 256>>>(Lms, Lmv, N);
    update_s_kernel<<<gN, 128>>>(node_s, node_v, W3ss, W3vvs, N);
    update_v_kernel<<<gN, 128>>>(node_s, node_v, W3sv, W3vs, W3vvv, N);
    final_kernel<<<(N + 255) / 256, 256>>>(Lus, Luv, out, N);
}